// round 4
// baseline (speedup 1.0000x reference)
#include <cuda_runtime.h>
#include <cstdint>

// ---------------- problem dims ----------------
#define MDIM 8192
#define NDIM 4096
#define KDIM 4096

// ---------------- tiling ----------------
#define BM 128
#define BN 256
#define BK 64
#define ROWB 80                            // padded row stride (64B data + 16B pad)
#define STAGES 4
#define NCHUNK (KDIM / BK)                 // 64
#define A_STAGE (BM * ROWB)                // 10240 B
#define B_STAGE (BN * ROWB)                // 20480 B
#define STAGE_BYTES (A_STAGE + B_STAGE)    // 30720 B
#define SMEM_DYN (STAGES * STAGE_BYTES)    // 122880 B

// ---------------- int8 staging (static device globals: no allocation) ----------------
__device__ int8_t g_A[(size_t)MDIM * KDIM];   // 32 MB
__device__ int8_t g_B[(size_t)NDIM * KDIM];   // 16 MB

// ---------------- PTX helpers (base-ISA only: cp.async / ldmatrix / mma.sync) -------
__device__ __forceinline__ uint32_t smem_u32(const void* p) {
    uint32_t a;
    asm("{ .reg .u64 t; cvta.to.shared.u64 t, %1; cvt.u32.u64 %0, t; }" : "=r"(a) : "l"(p));
    return a;
}

__device__ __forceinline__ void cp16(uint32_t dst, const void* src) {
    asm volatile("cp.async.cg.shared.global [%0], [%1], 16;" :: "r"(dst), "l"(src));
}
__device__ __forceinline__ void cp_commit() {
    asm volatile("cp.async.commit_group;" ::: "memory");
}
template <int N>
__device__ __forceinline__ void cp_wait() {
    asm volatile("cp.async.wait_group %0;" :: "n"(N) : "memory");
}

__device__ __forceinline__ void ldsm4(uint32_t* r, uint32_t addr) {
    asm volatile("ldmatrix.sync.aligned.m8n8.x4.shared.b16 {%0,%1,%2,%3}, [%4];"
                 : "=r"(r[0]), "=r"(r[1]), "=r"(r[2]), "=r"(r[3])
                 : "r"(addr));
}

__device__ __forceinline__ void mma_s8(int* d, const uint32_t* a, const uint32_t* b) {
    asm volatile("mma.sync.aligned.m16n8k32.row.col.s32.s8.s8.s32 "
                 "{%0,%1,%2,%3}, {%4,%5,%6,%7}, {%8,%9}, {%0,%1,%2,%3};"
                 : "+r"(d[0]), "+r"(d[1]), "+r"(d[2]), "+r"(d[3])
                 : "r"(a[0]), "r"(a[1]), "r"(a[2]), "r"(a[3]), "r"(b[0]), "r"(b[1]));
}

// ---------------- conversion kernels ----------------
__global__ void __launch_bounds__(256) cvt_x_kernel(const int4* __restrict__ x) {
    size_t i = (size_t)blockIdx.x * blockDim.x + threadIdx.x;   // over MDIM*KDIM/4
    int4 v = x[i];
    uint32_t p = (uint32_t)(v.x & 0xFF) | ((uint32_t)(v.y & 0xFF) << 8) |
                 ((uint32_t)(v.z & 0xFF) << 16) | ((uint32_t)v.w << 24);
    reinterpret_cast<uint32_t*>(g_A)[i] = p;
}

__global__ void __launch_bounds__(256) cvt_w_kernel(const float4* __restrict__ w) {
    size_t i = (size_t)blockIdx.x * blockDim.x + threadIdx.x;   // over NDIM*KDIM/4
    float4 v = w[i];
    int a0 = __float2int_rn(v.x), a1 = __float2int_rn(v.y);
    int a2 = __float2int_rn(v.z), a3 = __float2int_rn(v.w);
    uint32_t p = (uint32_t)(a0 & 0xFF) | ((uint32_t)(a1 & 0xFF) << 8) |
                 ((uint32_t)(a2 & 0xFF) << 16) | ((uint32_t)a3 << 24);
    reinterpret_cast<uint32_t*>(g_B)[i] = p;
}

// ---------------- GEMM kernel ----------------
__device__ __forceinline__ int clip8(int v) {
    return v < -128 ? -128 : (v > 127 ? 127 : v);
}

__global__ void __launch_bounds__(256, 1)
imma_gemm_kernel(const float* __restrict__ bias,
                 const float* __restrict__ alpha_p,
                 float* __restrict__ out) {
    extern __shared__ int8_t smem[];
    const uint32_t sbase = smem_u32(smem);

    const int tid  = threadIdx.x;
    const int lane = tid & 31;
    const int wid  = tid >> 5;
    const int wm   = wid >> 1;       // 0..3  (M warps, 32 rows each)
    const int wn   = wid & 1;        // 0..1  (N warps, 128 cols each)
    const int m_base = blockIdx.y * BM;
    const int n_base = blockIdx.x * BN;

    int acc[2][16][4];
    #pragma unroll
    for (int i = 0; i < 2; i++)
        #pragma unroll
        for (int j = 0; j < 16; j++)
            #pragma unroll
            for (int k = 0; k < 4; k++) acc[i][j][k] = 0;

    // --- ldmatrix per-thread address components (padded-row layout) ---
    const uint32_t arow   = (uint32_t)(wm * 32 + (lane & 15));
    const uint32_t akb_hi = (uint32_t)(lane >> 4);                 // 0/1 (k 16B half)
    const uint32_t a_off  = arow * ROWB + akb_hi * 16u;

    const uint32_t brow   = (uint32_t)(wn * 128 + (lane & 7) + ((lane >> 4) << 3));
    const uint32_t bkb_hi = (uint32_t)((lane >> 3) & 1);
    const uint32_t b_off  = brow * ROWB + bkb_hi * 16u;

    // --- stage loader: 1536 x 16B chunks, 6 per thread ---
    auto load_stage = [&](int kc, int st) {
        const uint32_t sb = sbase + (uint32_t)st * STAGE_BYTES;
        const int kbyte = kc * BK;
        #pragma unroll
        for (int i = 0; i < 6; i++) {
            int ch = tid + 256 * i;
            if (ch < 512) {   // A: 512 chunks (branch uniform per i)
                int row = ch >> 2, kb = ch & 3;
                cp16(sb + (uint32_t)row * ROWB + (uint32_t)kb * 16u,
                     g_A + (size_t)(m_base + row) * KDIM + kbyte + kb * 16);
            } else {          // B: 1024 chunks
                int c2 = ch - 512;
                int row = c2 >> 2, kb = c2 & 3;
                cp16(sb + A_STAGE + (uint32_t)row * ROWB + (uint32_t)kb * 16u,
                     g_B + (size_t)(n_base + row) * KDIM + kbyte + kb * 16);
            }
        }
        cp_commit();
    };

    // --- prologue: 3 stages in flight ---
    load_stage(0, 0);
    load_stage(1, 1);
    load_stage(2, 2);

    // --- mainloop ---
    for (int c = 0; c < NCHUNK; c++) {
        cp_wait<2>();
        __syncthreads();

        const uint32_t sb = sbase + (uint32_t)(c & 3) * STAGE_BYTES;
        #pragma unroll
        for (int s = 0; s < 2; s++) {
            uint32_t af[2][4];
            ldsm4(af[0], sb + a_off + (uint32_t)s * 32u);
            ldsm4(af[1], sb + a_off + (uint32_t)s * 32u + 16u * ROWB);
            #pragma unroll
            for (int j = 0; j < 8; j++) {
                uint32_t bf[4];
                ldsm4(bf, sb + A_STAGE + b_off + (uint32_t)s * 32u + (uint32_t)j * (16u * ROWB));
                mma_s8(acc[0][2 * j],     af[0], bf);
                mma_s8(acc[0][2 * j + 1], af[0], bf + 2);
                mma_s8(acc[1][2 * j],     af[1], bf);
                mma_s8(acc[1][2 * j + 1], af[1], bf + 2);
            }
        }

        __syncthreads();
        if (c + 3 < NCHUNK) load_stage(c + 3, (c + 3) & 3);
        else                cp_commit();   // keep group counting aligned
    }

    // --- epilogue: y = clip(round_half_even(acc*alpha + bias)), stored as FLOAT32 ---
    const float alphav = *alpha_p;
    const int g = lane >> 2, t = lane & 3;
    #pragma unroll
    for (int i = 0; i < 2; i++) {
        const size_t row0 = (size_t)(m_base + wm * 32 + i * 16 + g);
        #pragma unroll
        for (int j = 0; j < 16; j++) {
            const int nc = n_base + wn * 128 + j * 8 + 2 * t;
            const float b0 = __ldg(bias + nc);
            const float b1 = __ldg(bias + nc + 1);
            const int* a = acc[i][j];
            // exact: mul then add, matching reference's y*alpha + bias in fp32
            int v0 = clip8(__float2int_rn(__fadd_rn(__fmul_rn((float)a[0], alphav), b0)));
            int v1 = clip8(__float2int_rn(__fadd_rn(__fmul_rn((float)a[1], alphav), b1)));
            int v2 = clip8(__float2int_rn(__fadd_rn(__fmul_rn((float)a[2], alphav), b0)));
            int v3 = clip8(__float2int_rn(__fadd_rn(__fmul_rn((float)a[3], alphav), b1)));
            float2 lo = make_float2((float)v0, (float)v1);
            float2 hi = make_float2((float)v2, (float)v3);
            *reinterpret_cast<float2*>(out + row0 * NDIM + nc) = lo;
            *reinterpret_cast<float2*>(out + (row0 + 8) * NDIM + nc) = hi;
        }
    }
}

// ---------------- host launch ----------------
extern "C" void kernel_launch(void* const* d_in, const int* in_sizes, int n_in,
                              void* d_out, int out_size) {
    const int*   x     = (const int*)d_in[0];
    const float* w     = (const float*)d_in[1];
    const float* bias  = (const float*)d_in[2];
    const float* alpha = (const float*)d_in[3];
    float*       out   = (float*)d_out;

    // stage int8 conversions
    cvt_x_kernel<<<(unsigned)(((size_t)MDIM * KDIM / 4) / 256), 256>>>((const int4*)x);
    cvt_w_kernel<<<(unsigned)(((size_t)NDIM * KDIM / 4) / 256), 256>>>((const float4*)w);

    // set every call (non-stream API, capture-safe; no static guards per harness rules)
    cudaFuncSetAttribute(imma_gemm_kernel,
                         cudaFuncAttributeMaxDynamicSharedMemorySize, SMEM_DYN);

    dim3 grid(NDIM / BN, MDIM / BM);   // (16, 64) = 1024 CTAs
    imma_gemm_kernel<<<grid, 256, SMEM_DYN>>>(bias, alpha, out);
}

// round 5
// speedup vs baseline: 1.0500x; 1.0500x over previous
#include <cuda_runtime.h>
#include <cstdint>

// ---------------- problem dims ----------------
#define MDIM 8192
#define NDIM 4096
#define KDIM 4096

// ---------------- tiling ----------------
#define BM 128
#define BN 256
#define BK 64
#define ROWB 80                            // padded row stride (64B data + 16B pad)
#define STAGES 4
#define NCHUNK (KDIM / BK)                 // 64
#define A_STAGE (BM * ROWB)                // 10240 B
#define B_STAGE (BN * ROWB)                // 20480 B
#define STAGE_BYTES (A_STAGE + B_STAGE)    // 30720 B
#define SMEM_DYN (STAGES * STAGE_BYTES)    // 122880 B
#define THREADS 512

// ---------------- int8 staging (static device globals: no allocation) ----------------
__device__ int8_t g_A[(size_t)MDIM * KDIM];   // 32 MB
__device__ int8_t g_B[(size_t)NDIM * KDIM];   // 16 MB

// ---------------- PTX helpers (base-ISA only: cp.async / ldmatrix / mma.sync) -------
__device__ __forceinline__ uint32_t smem_u32(const void* p) {
    uint32_t a;
    asm("{ .reg .u64 t; cvta.to.shared.u64 t, %1; cvt.u32.u64 %0, t; }" : "=r"(a) : "l"(p));
    return a;
}

__device__ __forceinline__ void cp16(uint32_t dst, const void* src) {
    asm volatile("cp.async.cg.shared.global [%0], [%1], 16;" :: "r"(dst), "l"(src));
}
__device__ __forceinline__ void cp_commit() {
    asm volatile("cp.async.commit_group;" ::: "memory");
}
template <int N>
__device__ __forceinline__ void cp_wait() {
    asm volatile("cp.async.wait_group %0;" :: "n"(N) : "memory");
}

__device__ __forceinline__ void ldsm4(uint32_t* r, uint32_t addr) {
    asm volatile("ldmatrix.sync.aligned.m8n8.x4.shared.b16 {%0,%1,%2,%3}, [%4];"
                 : "=r"(r[0]), "=r"(r[1]), "=r"(r[2]), "=r"(r[3])
                 : "r"(addr));
}

__device__ __forceinline__ void mma_s8(int* d, const uint32_t* a, const uint32_t* b) {
    asm volatile("mma.sync.aligned.m16n8k32.row.col.s32.s8.s8.s32 "
                 "{%0,%1,%2,%3}, {%4,%5,%6,%7}, {%8,%9}, {%0,%1,%2,%3};"
                 : "+r"(d[0]), "+r"(d[1]), "+r"(d[2]), "+r"(d[3])
                 : "r"(a[0]), "r"(a[1]), "r"(a[2]), "r"(a[3]), "r"(b[0]), "r"(b[1]));
}

// ---------------- conversion kernels ----------------
__global__ void __launch_bounds__(256) cvt_x_kernel(const int4* __restrict__ x) {
    size_t i = (size_t)blockIdx.x * blockDim.x + threadIdx.x;   // over MDIM*KDIM/4
    int4 v = x[i];
    uint32_t p = (uint32_t)(v.x & 0xFF) | ((uint32_t)(v.y & 0xFF) << 8) |
                 ((uint32_t)(v.z & 0xFF) << 16) | ((uint32_t)v.w << 24);
    reinterpret_cast<uint32_t*>(g_A)[i] = p;
}

__global__ void __launch_bounds__(256) cvt_w_kernel(const float4* __restrict__ w) {
    size_t i = (size_t)blockIdx.x * blockDim.x + threadIdx.x;   // over NDIM*KDIM/4
    float4 v = w[i];
    int a0 = __float2int_rn(v.x), a1 = __float2int_rn(v.y);
    int a2 = __float2int_rn(v.z), a3 = __float2int_rn(v.w);
    uint32_t p = (uint32_t)(a0 & 0xFF) | ((uint32_t)(a1 & 0xFF) << 8) |
                 ((uint32_t)(a2 & 0xFF) << 16) | ((uint32_t)a3 << 24);
    reinterpret_cast<uint32_t*>(g_B)[i] = p;
}

// ---------------- GEMM kernel ----------------
__device__ __forceinline__ int clip8(int v) {
    return v < -128 ? -128 : (v > 127 ? 127 : v);
}

__global__ void __launch_bounds__(THREADS, 1)
imma_gemm_kernel(const float* __restrict__ bias,
                 const float* __restrict__ alpha_p,
                 float* __restrict__ out) {
    extern __shared__ int8_t smem[];
    const uint32_t sbase = smem_u32(smem);

    const int tid  = threadIdx.x;
    const int lane = tid & 31;
    const int wid  = tid >> 5;       // 0..15
    const int wm   = wid >> 2;       // 0..3  (M warps, 32 rows each)
    const int wn   = wid & 3;        // 0..3  (N warps, 64 cols each)
    const int m_base = blockIdx.y * BM;
    const int n_base = blockIdx.x * BN;

    int acc[2][8][4];
    #pragma unroll
    for (int i = 0; i < 2; i++)
        #pragma unroll
        for (int j = 0; j < 8; j++)
            #pragma unroll
            for (int k = 0; k < 4; k++) acc[i][j][k] = 0;

    // --- ldmatrix per-thread address components (padded-row layout) ---
    const uint32_t arow   = (uint32_t)(wm * 32 + (lane & 15));
    const uint32_t akb_hi = (uint32_t)(lane >> 4);                 // 0/1 (k 16B half)
    const uint32_t a_off  = arow * ROWB + akb_hi * 16u;

    const uint32_t brow   = (uint32_t)(wn * 64 + (lane & 7) + ((lane >> 4) << 3));
    const uint32_t bkb_hi = (uint32_t)((lane >> 3) & 1);
    const uint32_t b_off  = brow * ROWB + bkb_hi * 16u;

    // --- stage loader: 1536 x 16B chunks, 3 per thread ---
    auto load_stage = [&](int kc, int st) {
        const uint32_t sb = sbase + (uint32_t)st * STAGE_BYTES;
        const int kbyte = kc * BK;
        #pragma unroll
        for (int i = 0; i < 3; i++) {
            int ch = tid + THREADS * i;
            if (ch < 512) {   // A: 512 chunks (branch uniform: i==0)
                int row = ch >> 2, kb = ch & 3;
                cp16(sb + (uint32_t)row * ROWB + (uint32_t)kb * 16u,
                     g_A + (size_t)(m_base + row) * KDIM + kbyte + kb * 16);
            } else {          // B: 1024 chunks
                int c2 = ch - 512;
                int row = c2 >> 2, kb = c2 & 3;
                cp16(sb + A_STAGE + (uint32_t)row * ROWB + (uint32_t)kb * 16u,
                     g_B + (size_t)(n_base + row) * KDIM + kbyte + kb * 16);
            }
        }
        cp_commit();
    };

    // --- prologue: 3 stages in flight ---
    load_stage(0, 0);
    load_stage(1, 1);
    load_stage(2, 2);

    // --- mainloop ---
    for (int c = 0; c < NCHUNK; c++) {
        cp_wait<2>();
        __syncthreads();

        const uint32_t sb = sbase + (uint32_t)(c & 3) * STAGE_BYTES;
        #pragma unroll
        for (int s = 0; s < 2; s++) {
            uint32_t af[2][4];
            ldsm4(af[0], sb + a_off + (uint32_t)s * 32u);
            ldsm4(af[1], sb + a_off + (uint32_t)s * 32u + 16u * ROWB);
            #pragma unroll
            for (int j = 0; j < 4; j++) {
                uint32_t bf[4];
                ldsm4(bf, sb + A_STAGE + b_off + (uint32_t)s * 32u + (uint32_t)j * (16u * ROWB));
                mma_s8(acc[0][2 * j],     af[0], bf);
                mma_s8(acc[0][2 * j + 1], af[0], bf + 2);
                mma_s8(acc[1][2 * j],     af[1], bf);
                mma_s8(acc[1][2 * j + 1], af[1], bf + 2);
            }
        }

        // NOTE: no second barrier needed — next iteration's top __syncthreads
        // orders all reads of the stage being overwritten before the cp.async.
        if (c + 3 < NCHUNK) load_stage(c + 3, (c + 3) & 3);
        else                cp_commit();   // keep group counting aligned (load-bearing)
    }

    // --- epilogue: y = clip(round_half_even(acc*alpha + bias)), stored as FLOAT32 ---
    const float alphav = *alpha_p;
    const int g = lane >> 2, t = lane & 3;
    #pragma unroll
    for (int i = 0; i < 2; i++) {
        const size_t row0 = (size_t)(m_base + wm * 32 + i * 16 + g);
        #pragma unroll
        for (int j = 0; j < 8; j++) {
            const int nc = n_base + wn * 64 + j * 8 + 2 * t;
            const float b0 = __ldg(bias + nc);
            const float b1 = __ldg(bias + nc + 1);
            const int* a = acc[i][j];
            // exact: mul then add, matching reference's y*alpha + bias in fp32
            int v0 = clip8(__float2int_rn(__fadd_rn(__fmul_rn((float)a[0], alphav), b0)));
            int v1 = clip8(__float2int_rn(__fadd_rn(__fmul_rn((float)a[1], alphav), b1)));
            int v2 = clip8(__float2int_rn(__fadd_rn(__fmul_rn((float)a[2], alphav), b0)));
            int v3 = clip8(__float2int_rn(__fadd_rn(__fmul_rn((float)a[3], alphav), b1)));
            float2 lo = make_float2((float)v0, (float)v1);
            float2 hi = make_float2((float)v2, (float)v3);
            *reinterpret_cast<float2*>(out + row0 * NDIM + nc) = lo;
            *reinterpret_cast<float2*>(out + (row0 + 8) * NDIM + nc) = hi;
        }
    }
}

// ---------------- host launch ----------------
extern "C" void kernel_launch(void* const* d_in, const int* in_sizes, int n_in,
                              void* d_out, int out_size) {
    const int*   x     = (const int*)d_in[0];
    const float* w     = (const float*)d_in[1];
    const float* bias  = (const float*)d_in[2];
    const float* alpha = (const float*)d_in[3];
    float*       out   = (float*)d_out;

    // stage int8 conversions
    cvt_x_kernel<<<(unsigned)(((size_t)MDIM * KDIM / 4) / 256), 256>>>((const int4*)x);
    cvt_w_kernel<<<(unsigned)(((size_t)NDIM * KDIM / 4) / 256), 256>>>((const float4*)w);

    // set every call (non-stream API, capture-safe; no static guards per harness rules)
    cudaFuncSetAttribute(imma_gemm_kernel,
                         cudaFuncAttributeMaxDynamicSharedMemorySize, SMEM_DYN);

    dim3 grid(NDIM / BN, MDIM / BM);   // (16, 64) = 1024 CTAs
    imma_gemm_kernel<<<grid, THREADS, SMEM_DYN>>>(bias, alpha, out);
}

// round 6
// speedup vs baseline: 2.8354x; 2.7003x over previous
#include <cuda_runtime.h>
#include <cuda_bf16.h>
#include <cstdint>

// ---------------- problem dims ----------------
#define MDIM 8192
#define NDIM 4096
#define KDIM 4096

// ---------------- tiling ----------------
#define BM 128
#define BN 256
#define BK 64                              // K elements per chunk (bf16): 128B per row
#define ROWB 144                           // padded row stride (128B data + 16B pad)
#define STAGES 3
#define NCHUNK (KDIM / BK)                 // 64
#define A_STAGE (BM * ROWB)                // 18432 B
#define B_STAGE (BN * ROWB)                // 36864 B
#define STAGE_BYTES (A_STAGE + B_STAGE)    // 55296 B
#define SMEM_DYN (STAGES * STAGE_BYTES)    // 165888 B
#define THREADS 512

// ---------------- bf16 staging (static device globals: no allocation) ----------------
__device__ __nv_bfloat16 g_A[(size_t)MDIM * KDIM];   // 64 MB
__device__ __nv_bfloat16 g_B[(size_t)NDIM * KDIM];   // 32 MB

// ---------------- PTX helpers (base-ISA: cp.async / ldmatrix / mma.sync bf16) -------
__device__ __forceinline__ uint32_t smem_u32(const void* p) {
    uint32_t a;
    asm("{ .reg .u64 t; cvta.to.shared.u64 t, %1; cvt.u32.u64 %0, t; }" : "=r"(a) : "l"(p));
    return a;
}

__device__ __forceinline__ void cp16(uint32_t dst, const void* src) {
    asm volatile("cp.async.cg.shared.global [%0], [%1], 16;" :: "r"(dst), "l"(src));
}
__device__ __forceinline__ void cp_commit() {
    asm volatile("cp.async.commit_group;" ::: "memory");
}
template <int N>
__device__ __forceinline__ void cp_wait() {
    asm volatile("cp.async.wait_group %0;" :: "n"(N) : "memory");
}

__device__ __forceinline__ void ldsm4(uint32_t* r, uint32_t addr) {
    asm volatile("ldmatrix.sync.aligned.m8n8.x4.shared.b16 {%0,%1,%2,%3}, [%4];"
                 : "=r"(r[0]), "=r"(r[1]), "=r"(r[2]), "=r"(r[3])
                 : "r"(addr));
}

__device__ __forceinline__ void mma_bf16(float* d, const uint32_t* a, const uint32_t* b) {
    asm volatile("mma.sync.aligned.m16n8k16.row.col.f32.bf16.bf16.f32 "
                 "{%0,%1,%2,%3}, {%4,%5,%6,%7}, {%8,%9}, {%0,%1,%2,%3};"
                 : "+f"(d[0]), "+f"(d[1]), "+f"(d[2]), "+f"(d[3])
                 : "r"(a[0]), "r"(a[1]), "r"(a[2]), "r"(a[3]), "r"(b[0]), "r"(b[1]));
}

// ---------------- conversion kernels (int8-valued -> bf16, exact) ----------------
__global__ void __launch_bounds__(256) cvt_x_kernel(const int4* __restrict__ x) {
    size_t i = (size_t)blockIdx.x * blockDim.x + threadIdx.x;   // over MDIM*KDIM/4
    int4 v = x[i];
    union { __nv_bfloat162 h2[2]; uint2 u; } o;
    o.h2[0] = __floats2bfloat162_rn((float)v.x, (float)v.y);
    o.h2[1] = __floats2bfloat162_rn((float)v.z, (float)v.w);
    reinterpret_cast<uint2*>(g_A)[i] = o.u;
}

__global__ void __launch_bounds__(256) cvt_w_kernel(const float4* __restrict__ w) {
    size_t i = (size_t)blockIdx.x * blockDim.x + threadIdx.x;   // over NDIM*KDIM/4
    float4 v = w[i];
    union { __nv_bfloat162 h2[2]; uint2 u; } o;
    o.h2[0] = __floats2bfloat162_rn(v.x, v.y);
    o.h2[1] = __floats2bfloat162_rn(v.z, v.w);
    reinterpret_cast<uint2*>(g_B)[i] = o.u;
}

// ---------------- GEMM kernel ----------------
__device__ __forceinline__ int clip8(int v) {
    return v < -128 ? -128 : (v > 127 ? 127 : v);
}

__global__ void __launch_bounds__(THREADS, 1)
hmma_gemm_kernel(const float* __restrict__ bias,
                 const float* __restrict__ alpha_p,
                 float* __restrict__ out) {
    extern __shared__ int8_t smem[];
    const uint32_t sbase = smem_u32(smem);

    const int tid  = threadIdx.x;
    const int lane = tid & 31;
    const int wid  = tid >> 5;       // 0..15
    const int wm   = wid >> 2;       // 0..3  (M warps, 32 rows each)
    const int wn   = wid & 3;        // 0..3  (N warps, 64 cols each)
    const int m_base = blockIdx.y * BM;
    const int n_base = blockIdx.x * BN;

    float acc[2][8][4];
    #pragma unroll
    for (int i = 0; i < 2; i++)
        #pragma unroll
        for (int j = 0; j < 8; j++)
            #pragma unroll
            for (int k = 0; k < 4; k++) acc[i][j][k] = 0.0f;

    // --- ldmatrix per-thread address components (padded 144B rows) ---
    // A (m16k16 per step s): lanes 0-7 m0-7 k-lo16B; 8-15 m8-15 k-lo; 16-23 m0-7 k-hi; 24-31 m8-15 k-hi
    const uint32_t arow   = (uint32_t)(wm * 32 + (lane & 15));
    const uint32_t akb_hi = (uint32_t)(lane >> 4);                 // 0/1 (8-element k half)
    const uint32_t a_off  = arow * ROWB + akb_hi * 16u;           // + s*32 + i*(16*ROWB)

    // B (k16 x n16 per ldsm4): lanes0-7 n0-7 k-lo; 8-15 n0-7 k-hi; 16-23 n8-15 k-lo; 24-31 k-hi
    const uint32_t brow   = (uint32_t)(wn * 64 + (lane & 7) + ((lane >> 4) << 3));
    const uint32_t bkb_hi = (uint32_t)((lane >> 3) & 1);
    const uint32_t b_off  = brow * ROWB + bkb_hi * 16u;           // + s*32 + j*(16*ROWB)

    // --- stage loader: 3072 x 16B chunks, 6 per thread ---
    auto load_stage = [&](int kc, int st) {
        const uint32_t sb = sbase + (uint32_t)st * STAGE_BYTES;
        const int kel = kc * BK;                                   // k element offset
        #pragma unroll
        for (int i = 0; i < 6; i++) {
            int ch = tid + THREADS * i;
            if (ch < 1024) {   // A: 1024 chunks (branch uniform: i<2)
                int row = ch >> 3, kb = ch & 7;
                cp16(sb + (uint32_t)row * ROWB + (uint32_t)kb * 16u,
                     g_A + (size_t)(m_base + row) * KDIM + kel + kb * 8);
            } else {           // B: 2048 chunks
                int c2 = ch - 1024;
                int row = c2 >> 3, kb = c2 & 7;
                cp16(sb + A_STAGE + (uint32_t)row * ROWB + (uint32_t)kb * 16u,
                     g_B + (size_t)(n_base + row) * KDIM + kel + kb * 8);
            }
        }
        cp_commit();
    };

    // --- prologue: 2 stages in flight ---
    load_stage(0, 0);
    load_stage(1, 1);

    // --- mainloop ---
    int st = 0;
    for (int c = 0; c < NCHUNK; c++) {
        cp_wait<1>();
        __syncthreads();

        const uint32_t sb = sbase + (uint32_t)st * STAGE_BYTES;
        #pragma unroll
        for (int s = 0; s < 4; s++) {                      // 4 k16 steps per 64-chunk
            uint32_t af[2][4];
            ldsm4(af[0], sb + a_off + (uint32_t)s * 32u);
            ldsm4(af[1], sb + a_off + (uint32_t)s * 32u + 16u * ROWB);
            #pragma unroll
            for (int j = 0; j < 4; j++) {                  // 4 n16 pairs = 64 n
                uint32_t bf[4];
                ldsm4(bf, sb + A_STAGE + b_off + (uint32_t)s * 32u + (uint32_t)j * (16u * ROWB));
                mma_bf16(acc[0][2 * j],     af[0], bf);
                mma_bf16(acc[0][2 * j + 1], af[0], bf + 2);
                mma_bf16(acc[1][2 * j],     af[1], bf);
                mma_bf16(acc[1][2 * j + 1], af[1], bf + 2);
            }
        }

        // next-iteration top barrier orders these reads before slot reuse
        if (c + 2 < NCHUNK) load_stage(c + 2, (c + 2) % STAGES);
        else                cp_commit();   // keep wait_group counting aligned
        st = (st + 1 == STAGES) ? 0 : st + 1;
    }

    // --- epilogue: y = clip(round_half_even(acc*alpha + bias)), stored as FLOAT32 ---
    const float alphav = *alpha_p;
    const int g = lane >> 2, t = lane & 3;
    #pragma unroll
    for (int i = 0; i < 2; i++) {
        const size_t row0 = (size_t)(m_base + wm * 32 + i * 16 + g);
        #pragma unroll
        for (int j = 0; j < 8; j++) {
            const int nc = n_base + wn * 64 + j * 8 + 2 * t;
            const float b0 = __ldg(bias + nc);
            const float b1 = __ldg(bias + nc + 1);
            const float* a = acc[i][j];
            int v0 = clip8(__float2int_rn(__fadd_rn(__fmul_rn(a[0], alphav), b0)));
            int v1 = clip8(__float2int_rn(__fadd_rn(__fmul_rn(a[1], alphav), b1)));
            int v2 = clip8(__float2int_rn(__fadd_rn(__fmul_rn(a[2], alphav), b0)));
            int v3 = clip8(__float2int_rn(__fadd_rn(__fmul_rn(a[3], alphav), b1)));
            float2 lo = make_float2((float)v0, (float)v1);
            float2 hi = make_float2((float)v2, (float)v3);
            *reinterpret_cast<float2*>(out + row0 * NDIM + nc) = lo;
            *reinterpret_cast<float2*>(out + (row0 + 8) * NDIM + nc) = hi;
        }
    }
}

// ---------------- host launch ----------------
extern "C" void kernel_launch(void* const* d_in, const int* in_sizes, int n_in,
                              void* d_out, int out_size) {
    const int*   x     = (const int*)d_in[0];
    const float* w     = (const float*)d_in[1];
    const float* bias  = (const float*)d_in[2];
    const float* alpha = (const float*)d_in[3];
    float*       out   = (float*)d_out;

    // stage bf16 conversions
    cvt_x_kernel<<<(unsigned)(((size_t)MDIM * KDIM / 4) / 256), 256>>>((const int4*)x);
    cvt_w_kernel<<<(unsigned)(((size_t)NDIM * KDIM / 4) / 256), 256>>>((const float4*)w);

    // set every call (non-stream API, capture-safe; no static guards per harness rules)
    cudaFuncSetAttribute(hmma_gemm_kernel,
                         cudaFuncAttributeMaxDynamicSharedMemorySize, SMEM_DYN);

    dim3 grid(NDIM / BN, MDIM / BM);   // (16, 64) = 1024 CTAs
    hmma_gemm_kernel<<<grid, THREADS, SMEM_DYN>>>(bias, alpha, out);
}

// round 7
// speedup vs baseline: 2.9181x; 1.0291x over previous
#include <cuda_runtime.h>
#include <cuda_bf16.h>
#include <cstdint>

// ---------------- problem dims ----------------
#define MDIM 8192
#define NDIM 4096
#define KDIM 4096

// ---------------- tiling ----------------
#define BM 128
#define BN 128
#define BK 64                              // K elements per chunk (bf16): 128B per row
#define ROWB 144                           // padded row stride (128B data + 16B pad)
#define STAGES 3
#define NCHUNK (KDIM / BK)                 // 64
#define A_STAGE (BM * ROWB)                // 18432 B
#define B_STAGE (BN * ROWB)                // 18432 B
#define STAGE_BYTES (A_STAGE + B_STAGE)    // 36864 B
#define SMEM_DYN (STAGES * STAGE_BYTES)    // 110592 B -> 2 CTAs/SM
#define THREADS 256

// ---------------- bf16 staging (static device globals: no allocation) ----------------
__device__ __nv_bfloat16 g_A[(size_t)MDIM * KDIM];   // 64 MB
__device__ __nv_bfloat16 g_B[(size_t)NDIM * KDIM];   // 32 MB

// ---------------- PTX helpers (base-ISA: cp.async / ldmatrix / mma.sync bf16) -------
__device__ __forceinline__ uint32_t smem_u32(const void* p) {
    uint32_t a;
    asm("{ .reg .u64 t; cvta.to.shared.u64 t, %1; cvt.u32.u64 %0, t; }" : "=r"(a) : "l"(p));
    return a;
}

__device__ __forceinline__ void cp16(uint32_t dst, const void* src) {
    asm volatile("cp.async.cg.shared.global [%0], [%1], 16;" :: "r"(dst), "l"(src));
}
__device__ __forceinline__ void cp_commit() {
    asm volatile("cp.async.commit_group;" ::: "memory");
}
template <int N>
__device__ __forceinline__ void cp_wait() {
    asm volatile("cp.async.wait_group %0;" :: "n"(N) : "memory");
}

__device__ __forceinline__ void ldsm4(uint32_t* r, uint32_t addr) {
    asm volatile("ldmatrix.sync.aligned.m8n8.x4.shared.b16 {%0,%1,%2,%3}, [%4];"
                 : "=r"(r[0]), "=r"(r[1]), "=r"(r[2]), "=r"(r[3])
                 : "r"(addr));
}

__device__ __forceinline__ void mma_bf16(float* d, const uint32_t* a, const uint32_t* b) {
    asm volatile("mma.sync.aligned.m16n8k16.row.col.f32.bf16.bf16.f32 "
                 "{%0,%1,%2,%3}, {%4,%5,%6,%7}, {%8,%9}, {%0,%1,%2,%3};"
                 : "+f"(d[0]), "+f"(d[1]), "+f"(d[2]), "+f"(d[3])
                 : "r"(a[0]), "r"(a[1]), "r"(a[2]), "r"(a[3]), "r"(b[0]), "r"(b[1]));
}

// ---------------- conversion kernels (int8-valued -> bf16, exact) ----------------
__global__ void __launch_bounds__(256) cvt_x_kernel(const int4* __restrict__ x) {
    size_t i = (size_t)blockIdx.x * blockDim.x + threadIdx.x;   // over MDIM*KDIM/4
    int4 v = x[i];
    union { __nv_bfloat162 h2[2]; uint2 u; } o;
    o.h2[0] = __floats2bfloat162_rn((float)v.x, (float)v.y);
    o.h2[1] = __floats2bfloat162_rn((float)v.z, (float)v.w);
    reinterpret_cast<uint2*>(g_A)[i] = o.u;
}

__global__ void __launch_bounds__(256) cvt_w_kernel(const float4* __restrict__ w) {
    size_t i = (size_t)blockIdx.x * blockDim.x + threadIdx.x;   // over NDIM*KDIM/4
    float4 v = w[i];
    union { __nv_bfloat162 h2[2]; uint2 u; } o;
    o.h2[0] = __floats2bfloat162_rn(v.x, v.y);
    o.h2[1] = __floats2bfloat162_rn(v.z, v.w);
    reinterpret_cast<uint2*>(g_B)[i] = o.u;
}

// ---------------- GEMM kernel ----------------
__device__ __forceinline__ int clip8(int v) {
    return v < -128 ? -128 : (v > 127 ? 127 : v);
}

__global__ void __launch_bounds__(THREADS, 2)
hmma_gemm_kernel(const float* __restrict__ bias,
                 const float* __restrict__ alpha_p,
                 float* __restrict__ out) {
    extern __shared__ int8_t smem[];
    const uint32_t sbase = smem_u32(smem);

    const int tid  = threadIdx.x;
    const int lane = tid & 31;
    const int wid  = tid >> 5;       // 0..7
    const int wm   = wid >> 1;       // 0..3  (M warps, 32 rows each)
    const int wn   = wid & 1;        // 0..1  (N warps, 64 cols each)
    const int m_base = blockIdx.y * BM;
    const int n_base = blockIdx.x * BN;

    float acc[2][8][4];
    #pragma unroll
    for (int i = 0; i < 2; i++)
        #pragma unroll
        for (int j = 0; j < 8; j++)
            #pragma unroll
            for (int k = 0; k < 4; k++) acc[i][j][k] = 0.0f;

    // --- ldmatrix per-thread address components (padded 144B rows) ---
    const uint32_t arow   = (uint32_t)(wm * 32 + (lane & 15));
    const uint32_t akb_hi = (uint32_t)(lane >> 4);                 // 0/1 (8-element k half)
    const uint32_t a_off  = arow * ROWB + akb_hi * 16u;           // + s*32 + i*(16*ROWB)

    const uint32_t brow   = (uint32_t)(wn * 64 + (lane & 7) + ((lane >> 4) << 3));
    const uint32_t bkb_hi = (uint32_t)((lane >> 3) & 1);
    const uint32_t b_off  = brow * ROWB + bkb_hi * 16u;           // + s*32 + j*(16*ROWB)

    // --- stage loader: 2048 x 16B chunks, 8 per thread ---
    auto load_stage = [&](int kc, int st) {
        const uint32_t sb = sbase + (uint32_t)st * STAGE_BYTES;
        const int kel = kc * BK;                                   // k element offset
        #pragma unroll
        for (int i = 0; i < 8; i++) {
            int ch = tid + THREADS * i;
            if (ch < 1024) {   // A: 1024 chunks (branch uniform: i<4)
                int row = ch >> 3, kb = ch & 7;
                cp16(sb + (uint32_t)row * ROWB + (uint32_t)kb * 16u,
                     g_A + (size_t)(m_base + row) * KDIM + kel + kb * 8);
            } else {           // B: 1024 chunks
                int c2 = ch - 1024;
                int row = c2 >> 3, kb = c2 & 7;
                cp16(sb + A_STAGE + (uint32_t)row * ROWB + (uint32_t)kb * 16u,
                     g_B + (size_t)(n_base + row) * KDIM + kel + kb * 8);
            }
        }
        cp_commit();
    };

    // --- prologue: 2 stages in flight ---
    load_stage(0, 0);
    load_stage(1, 1);

    // --- mainloop ---
    int st = 0;
    for (int c = 0; c < NCHUNK; c++) {
        cp_wait<1>();
        __syncthreads();

        const uint32_t sb = sbase + (uint32_t)st * STAGE_BYTES;
        #pragma unroll
        for (int s = 0; s < 4; s++) {                      // 4 k16 steps per 64-chunk
            uint32_t af[2][4];
            ldsm4(af[0], sb + a_off + (uint32_t)s * 32u);
            ldsm4(af[1], sb + a_off + (uint32_t)s * 32u + 16u * ROWB);
            #pragma unroll
            for (int j = 0; j < 4; j++) {                  // 4 n16 pairs = 64 n
                uint32_t bf[4];
                ldsm4(bf, sb + A_STAGE + b_off + (uint32_t)s * 32u + (uint32_t)j * (16u * ROWB));
                mma_bf16(acc[0][2 * j],     af[0], bf);
                mma_bf16(acc[0][2 * j + 1], af[0], bf + 2);
                mma_bf16(acc[1][2 * j],     af[1], bf);
                mma_bf16(acc[1][2 * j + 1], af[1], bf + 2);
            }
        }

        // slot (c+2)%3 was last read in iter c-1, ordered by this iter's top barrier
        if (c + 2 < NCHUNK) load_stage(c + 2, (c + 2) % STAGES);
        else                cp_commit();   // keep wait_group counting aligned
        st = (st + 1 == STAGES) ? 0 : st + 1;
    }

    // --- epilogue: y = clip(round_half_even(acc*alpha + bias)), stored as FLOAT32 ---
    const float alphav = *alpha_p;
    const int g = lane >> 2, t = lane & 3;
    #pragma unroll
    for (int i = 0; i < 2; i++) {
        const size_t row0 = (size_t)(m_base + wm * 32 + i * 16 + g);
        #pragma unroll
        for (int j = 0; j < 8; j++) {
            const int nc = n_base + wn * 64 + j * 8 + 2 * t;
            const float b0 = __ldg(bias + nc);
            const float b1 = __ldg(bias + nc + 1);
            const float* a = acc[i][j];
            int v0 = clip8(__float2int_rn(__fadd_rn(__fmul_rn(a[0], alphav), b0)));
            int v1 = clip8(__float2int_rn(__fadd_rn(__fmul_rn(a[1], alphav), b1)));
            int v2 = clip8(__float2int_rn(__fadd_rn(__fmul_rn(a[2], alphav), b0)));
            int v3 = clip8(__float2int_rn(__fadd_rn(__fmul_rn(a[3], alphav), b1)));
            float2 lo = make_float2((float)v0, (float)v1);
            float2 hi = make_float2((float)v2, (float)v3);
            *reinterpret_cast<float2*>(out + row0 * NDIM + nc) = lo;
            *reinterpret_cast<float2*>(out + (row0 + 8) * NDIM + nc) = hi;
        }
    }
}

// ---------------- host launch ----------------
extern "C" void kernel_launch(void* const* d_in, const int* in_sizes, int n_in,
                              void* d_out, int out_size) {
    const int*   x     = (const int*)d_in[0];
    const float* w     = (const float*)d_in[1];
    const float* bias  = (const float*)d_in[2];
    const float* alpha = (const float*)d_in[3];
    float*       out   = (float*)d_out;

    // stage bf16 conversions
    cvt_x_kernel<<<(unsigned)(((size_t)MDIM * KDIM / 4) / 256), 256>>>((const int4*)x);
    cvt_w_kernel<<<(unsigned)(((size_t)NDIM * KDIM / 4) / 256), 256>>>((const float4*)w);

    // set every call (non-stream API, capture-safe; no static guards per harness rules)
    cudaFuncSetAttribute(hmma_gemm_kernel,
                         cudaFuncAttributeMaxDynamicSharedMemorySize, SMEM_DYN);

    dim3 grid(NDIM / BN, MDIM / BM);   // (32, 64) = 2048 CTAs
    hmma_gemm_kernel<<<grid, THREADS, SMEM_DYN>>>(bias, alpha, out);
}